// round 1
// baseline (speedup 1.0000x reference)
#include <cuda_runtime.h>

typedef unsigned long long u64;

#define WPAD 132          // padded row length for W in smem (conflict-free + 16B aligned)
#define KB_STEPS 4        // 128 / 32

// scratch for the 3 transposed inverses (no cudaMalloc allowed)
__device__ float g_invgT[3 * 128 * 128];

__device__ __forceinline__ u64 dup2(float w) {
    u64 r;
    asm("mov.b64 %0, {%1, %1};" : "=l"(r) : "f"(w));
    return r;
}
__device__ __forceinline__ void ffma2(u64 &c, u64 a, u64 b) {
    asm("fma.rn.f32x2 %0, %1, %2, %0;" : "+l"(c) : "l"(a), "l"(b));
}

// ---------------------------------------------------------------------------
// Gauss-Jordan inversion of one 128x128 per block, rows register-resident.
// Thread t owns rows {rb, rb+32, rb+64, rb+96} (rb = t>>3), columns
// [c0, c0+32) of the augmented [128 x 256] matrix (c0 = (t&7)*32).
// Writes inv(g) TRANSPOSED (k-major) so the GEMM can copy it straight in.
// ---------------------------------------------------------------------------
__global__ void __launch_bounds__(256) invert_kernel(const float* __restrict__ G0,
                                                     const float* __restrict__ G1,
                                                     const float* __restrict__ G2)
{
    __shared__ float rowk[256];
    __shared__ float colk[128];
    const float* G = blockIdx.x == 0 ? G0 : (blockIdx.x == 1 ? G1 : G2);
    const int tid = threadIdx.x;
    const int cg = tid & 7;
    const int c0 = cg * 32;
    const int rb = tid >> 3;

    float r[4][32];
#pragma unroll
    for (int a = 0; a < 4; a++) {
        const int i = rb + 32 * a;
#pragma unroll
        for (int c = 0; c < 32; c++) {
            const int gc = c0 + c;
            r[a][c] = (gc < 128) ? G[i * 128 + gc] : ((gc - 128 == i) ? 1.0f : 0.0f);
        }
    }

    for (int k = 0; k < 128; k++) {
        // publish (unnormalized) pivot row and pivot column
        if ((k & 31) == rb) {
            const int a = k >> 5;
#pragma unroll
            for (int c = 0; c < 32; c++) rowk[c0 + c] = r[a][c];
        }
        if (cg == (k >> 5)) {
            const int cc = k & 31;
#pragma unroll
            for (int a = 0; a < 4; a++) colk[rb + 32 * a] = r[a][cc];
        }
        __syncthreads();

        const float rinv = 1.0f / rowk[k];
        // active column window is [k, k+128]; everything else is exactly 0
        const bool active = (c0 + 31 >= k) && (c0 <= k + 128);
        if (active) {
            float rk[32];
#pragma unroll
            for (int c = 0; c < 32; c++) rk[c] = rowk[c0 + c];
#pragma unroll
            for (int a = 0; a < 4; a++) {
                const int i = rb + 32 * a;
                if (i == k) {
#pragma unroll
                    for (int c = 0; c < 32; c++) r[a][c] *= rinv;
                } else {
                    const float m = colk[i] * rinv;
#pragma unroll
                    for (int c = 0; c < 32; c++) r[a][c] -= m * rk[c];
                }
            }
        }
        __syncthreads();
    }

    // right half of augmented matrix = inverse; store transposed (k-major)
    if (c0 >= 128) {
#pragma unroll
        for (int a = 0; a < 4; a++) {
            const int i = rb + 32 * a;
#pragma unroll
            for (int c = 0; c < 32; c++)
                g_invgT[blockIdx.x * (128 * 128) + (c0 - 128 + c) * 128 + i] = r[a][c];
        }
    }
}

// ---------------------------------------------------------------------------
// C[i, c] = sum_k Wt[k, i] * S[k, c]     (Wt is k-major: Wt[k*128 + i])
// Block: all 128 rows x 128-col tile. 256 threads, 8x8 outputs each, packed
// f32x2 accumulation. W cached in padded smem; S double-buffered 32x128.
// Used for both vn (Wt = g, M=512) and sn (Wt = invgT, M=262144).
// ---------------------------------------------------------------------------
__global__ void __launch_bounds__(256) gemm128(
    const float* __restrict__ W0, const float* __restrict__ W1, const float* __restrict__ W2,
    const float* __restrict__ S0, const float* __restrict__ S1, const float* __restrict__ S2,
    float* __restrict__ out, long comp_stride, int M)
{
    extern __shared__ float sm[];
    float* Wt = sm;                    // [128][WPAD]
    float* Ss = sm + 128 * WPAD;       // [2][32][128]

    const int tid = threadIdx.x;
    const int comp = blockIdx.y;
    const float* W = comp == 0 ? W0 : (comp == 1 ? W1 : W2);
    const float* S = comp == 0 ? S0 : (comp == 1 ? S1 : S2);
    float* oc = out + (long)comp * comp_stride;
    const long ct = (long)blockIdx.x * 128;

    // stage W into padded smem, k-major (source already k-major)
#pragma unroll
    for (int q = 0; q < 16; q++) {
        const int idx4 = tid + 256 * q;            // float4 index, 4096 total
        const int k = idx4 >> 5;
        const int i = (idx4 & 31) * 4;
        const float4 v = reinterpret_cast<const float4*>(W)[idx4];
        *reinterpret_cast<float4*>(&Wt[k * WPAD + i]) = v;
    }

    float4 pf0, pf1, pf2, pf3;
    auto ldS = [&](int kb) {
        const long base = (long)(kb * 32) * M + ct;
        pf0 = *reinterpret_cast<const float4*>(&S[base + (long)((tid +   0) >> 5) * M + ((tid +   0) & 31) * 4]);
        pf1 = *reinterpret_cast<const float4*>(&S[base + (long)((tid + 256) >> 5) * M + ((tid + 256) & 31) * 4]);
        pf2 = *reinterpret_cast<const float4*>(&S[base + (long)((tid + 512) >> 5) * M + ((tid + 512) & 31) * 4]);
        pf3 = *reinterpret_cast<const float4*>(&S[base + (long)((tid + 768) >> 5) * M + ((tid + 768) & 31) * 4]);
    };
    auto stS = [&](int buf) {
        float* b = &Ss[buf * 4096];
        *reinterpret_cast<float4*>(&b[((tid +   0) >> 5) * 128 + ((tid +   0) & 31) * 4]) = pf0;
        *reinterpret_cast<float4*>(&b[((tid + 256) >> 5) * 128 + ((tid + 256) & 31) * 4]) = pf1;
        *reinterpret_cast<float4*>(&b[((tid + 512) >> 5) * 128 + ((tid + 512) & 31) * 4]) = pf2;
        *reinterpret_cast<float4*>(&b[((tid + 768) >> 5) * 128 + ((tid + 768) & 31) * 4]) = pf3;
    };

    ldS(0);
    stS(0);
    __syncthreads();

    const int i0 = (tid >> 4) * 8;
    const int c0 = (tid & 15) * 8;

    u64 acc[8][4];
#pragma unroll
    for (int i = 0; i < 8; i++)
#pragma unroll
        for (int c = 0; c < 4; c++) acc[i][c] = 0ull;

    for (int kb = 0; kb < KB_STEPS; kb++) {
        if (kb + 1 < KB_STEPS) ldS(kb + 1);
        const float* wbase = &Wt[(kb * 32) * WPAD + i0];
        const float* sbase = &Ss[(kb & 1) * 4096 + c0];
#pragma unroll 8
        for (int kk = 0; kk < 32; kk++) {
            const float4 wa = *reinterpret_cast<const float4*>(wbase + kk * WPAD);
            const float4 wb = *reinterpret_cast<const float4*>(wbase + kk * WPAD + 4);
            const u64* sp = reinterpret_cast<const u64*>(sbase + kk * 128);
            const u64 sv0 = sp[0], sv1 = sp[1], sv2 = sp[2], sv3 = sp[3];
            u64 w;
            w = dup2(wa.x); ffma2(acc[0][0], sv0, w); ffma2(acc[0][1], sv1, w); ffma2(acc[0][2], sv2, w); ffma2(acc[0][3], sv3, w);
            w = dup2(wa.y); ffma2(acc[1][0], sv0, w); ffma2(acc[1][1], sv1, w); ffma2(acc[1][2], sv2, w); ffma2(acc[1][3], sv3, w);
            w = dup2(wa.z); ffma2(acc[2][0], sv0, w); ffma2(acc[2][1], sv1, w); ffma2(acc[2][2], sv2, w); ffma2(acc[2][3], sv3, w);
            w = dup2(wa.w); ffma2(acc[3][0], sv0, w); ffma2(acc[3][1], sv1, w); ffma2(acc[3][2], sv2, w); ffma2(acc[3][3], sv3, w);
            w = dup2(wb.x); ffma2(acc[4][0], sv0, w); ffma2(acc[4][1], sv1, w); ffma2(acc[4][2], sv2, w); ffma2(acc[4][3], sv3, w);
            w = dup2(wb.y); ffma2(acc[5][0], sv0, w); ffma2(acc[5][1], sv1, w); ffma2(acc[5][2], sv2, w); ffma2(acc[5][3], sv3, w);
            w = dup2(wb.z); ffma2(acc[6][0], sv0, w); ffma2(acc[6][1], sv1, w); ffma2(acc[6][2], sv2, w); ffma2(acc[6][3], sv3, w);
            w = dup2(wb.w); ffma2(acc[7][0], sv0, w); ffma2(acc[7][1], sv1, w); ffma2(acc[7][2], sv2, w); ffma2(acc[7][3], sv3, w);
        }
        if (kb + 1 < KB_STEPS) {
            __syncthreads();
            stS((kb + 1) & 1);
            __syncthreads();
        }
    }

#pragma unroll
    for (int i = 0; i < 8; i++) {
        u64* op = reinterpret_cast<u64*>(&oc[(long)(i0 + i) * M + ct + c0]);
        op[0] = acc[i][0]; op[1] = acc[i][1]; op[2] = acc[i][2]; op[3] = acc[i][3];
    }
}

// ---------------------------------------------------------------------------
// Inputs (metadata order): g0,g1,g2 (128x128), v0,v1,v2 (128x512),
// s0,s1,s2 (128x512x512). Output: [v0', s0', v1', s1', v2', s2'] flattened.
// ---------------------------------------------------------------------------
extern "C" void kernel_launch(void* const* d_in, const int* in_sizes, int n_in,
                              void* d_out, int out_size)
{
    const float* g0 = (const float*)d_in[0];
    const float* g1 = (const float*)d_in[1];
    const float* g2 = (const float*)d_in[2];
    const float* v0 = (const float*)d_in[3];
    const float* v1 = (const float*)d_in[4];
    const float* v2 = (const float*)d_in[5];
    const float* s0 = (const float*)d_in[6];
    const float* s1 = (const float*)d_in[7];
    const float* s2 = (const float*)d_in[8];
    float* out = (float*)d_out;

    const size_t SMEM = (size_t)(128 * WPAD + 2 * 32 * 128) * sizeof(float); // 100352 B
    cudaFuncSetAttribute(gemm128, cudaFuncAttributeMaxDynamicSharedMemorySize, (int)SMEM);

    void* invp = nullptr;
    cudaGetSymbolAddress(&invp, g_invgT);
    const float* ig = (const float*)invp;

    const long comp_stride = 65536L + 33554432L;   // one (v', s') section per component

    // vn = g^T v : Wt source is g itself (g[k*128+i] == g^T[i][k]); M = 512
    gemm128<<<dim3(4, 3), 256, SMEM>>>(g0, g1, g2, v0, v1, v2, out, comp_stride, 512);

    // invert the three g's (transposed result into g_invgT)
    invert_kernel<<<3, 256>>>(g0, g1, g2);

    // sn = inv(g) s : Wt source = invgT per component; M = 512*512
    gemm128<<<dim3(2048, 3), 256, SMEM>>>(ig, ig + 16384, ig + 32768,
                                          s0, s1, s2, out + 65536, comp_stride, 262144);
}

// round 2
// speedup vs baseline: 1.0030x; 1.0030x over previous
#include <cuda_runtime.h>

typedef unsigned long long u64;

#define WPAD 132          // padded row length for W in smem (conflict-free + 16B aligned)
#define KB_STEPS 4        // 128 / 32

// scratch for the 3 transposed inverses (no cudaMalloc allowed)
__device__ float g_invgT[3 * 128 * 128];

__device__ __forceinline__ u64 dup2(float w) {
    u64 r;
    asm("mov.b64 %0, {%1, %1};" : "=l"(r) : "f"(w));
    return r;
}
__device__ __forceinline__ void ffma2(u64 &c, u64 a, u64 b) {
    asm("fma.rn.f32x2 %0, %1, %2, %0;" : "+l"(c) : "l"(a), "l"(b));
}

// ---------------------------------------------------------------------------
// Gauss-Jordan inversion of one 128x128 per block, rows register-resident.
// Thread t owns rows {rb, rb+32, rb+64, rb+96} (rb = t>>3), columns
// [c0, c0+32) of the augmented [128 x 256] matrix (c0 = (t&7)*32).
// Writes inv(g) TRANSPOSED (k-major) so the GEMM can copy it straight in.
// ---------------------------------------------------------------------------
__global__ void __launch_bounds__(256) invert_kernel(const float* __restrict__ G0,
                                                     const float* __restrict__ G1,
                                                     const float* __restrict__ G2)
{
    __shared__ float rowk[256];
    __shared__ float colk[128];
    const float* G = blockIdx.x == 0 ? G0 : (blockIdx.x == 1 ? G1 : G2);
    const int tid = threadIdx.x;
    const int cg = tid & 7;
    const int c0 = cg * 32;
    const int rb = tid >> 3;

    float r[4][32];
#pragma unroll
    for (int a = 0; a < 4; a++) {
        const int i = rb + 32 * a;
#pragma unroll
        for (int c = 0; c < 32; c++) {
            const int gc = c0 + c;
            r[a][c] = (gc < 128) ? G[i * 128 + gc] : ((gc - 128 == i) ? 1.0f : 0.0f);
        }
    }

    for (int k = 0; k < 128; k++) {
        // publish (unnormalized) pivot row and pivot column
        if ((k & 31) == rb) {
            const int a = k >> 5;
#pragma unroll
            for (int c = 0; c < 32; c++) rowk[c0 + c] = r[a][c];
        }
        if (cg == (k >> 5)) {
            const int cc = k & 31;
#pragma unroll
            for (int a = 0; a < 4; a++) colk[rb + 32 * a] = r[a][cc];
        }
        __syncthreads();

        const float rinv = 1.0f / rowk[k];
        // active column window is [k, k+128]; everything else is exactly 0
        const bool active = (c0 + 31 >= k) && (c0 <= k + 128);
        if (active) {
            float rk[32];
#pragma unroll
            for (int c = 0; c < 32; c++) rk[c] = rowk[c0 + c];
#pragma unroll
            for (int a = 0; a < 4; a++) {
                const int i = rb + 32 * a;
                if (i == k) {
#pragma unroll
                    for (int c = 0; c < 32; c++) r[a][c] *= rinv;
                } else {
                    const float m = colk[i] * rinv;
#pragma unroll
                    for (int c = 0; c < 32; c++) r[a][c] -= m * rk[c];
                }
            }
        }
        __syncthreads();
    }

    // right half of augmented matrix = inverse; store transposed (k-major)
    if (c0 >= 128) {
#pragma unroll
        for (int a = 0; a < 4; a++) {
            const int i = rb + 32 * a;
#pragma unroll
            for (int c = 0; c < 32; c++)
                g_invgT[blockIdx.x * (128 * 128) + (c0 - 128 + c) * 128 + i] = r[a][c];
        }
    }
}

// ---------------------------------------------------------------------------
// C[i, c] = sum_k Wt[k, i] * S[k, c]     (Wt is k-major: Wt[k*128 + i])
// Block: all 128 rows x 128-col tile. 256 threads, 8x8 outputs each, packed
// f32x2 accumulation. W cached in padded smem; S double-buffered 32x128.
// Used for both vn (Wt = g, M=512) and sn (Wt = invgT, M=262144).
// ---------------------------------------------------------------------------
__global__ void __launch_bounds__(256) gemm128(
    const float* __restrict__ W0, const float* __restrict__ W1, const float* __restrict__ W2,
    const float* __restrict__ S0, const float* __restrict__ S1, const float* __restrict__ S2,
    float* __restrict__ out, long comp_stride, int M)
{
    extern __shared__ float sm[];
    float* Wt = sm;                    // [128][WPAD]
    float* Ss = sm + 128 * WPAD;       // [2][32][128]

    const int tid = threadIdx.x;
    const int comp = blockIdx.y;
    const float* W = comp == 0 ? W0 : (comp == 1 ? W1 : W2);
    const float* S = comp == 0 ? S0 : (comp == 1 ? S1 : S2);
    float* oc = out + (long)comp * comp_stride;
    const long ct = (long)blockIdx.x * 128;

    // stage W into padded smem, k-major (source already k-major)
#pragma unroll
    for (int q = 0; q < 16; q++) {
        const int idx4 = tid + 256 * q;            // float4 index, 4096 total
        const int k = idx4 >> 5;
        const int i = (idx4 & 31) * 4;
        const float4 v = reinterpret_cast<const float4*>(W)[idx4];
        *reinterpret_cast<float4*>(&Wt[k * WPAD + i]) = v;
    }

    float4 pf0, pf1, pf2, pf3;
    auto ldS = [&](int kb) {
        const long base = (long)(kb * 32) * M + ct;
        pf0 = *reinterpret_cast<const float4*>(&S[base + (long)((tid +   0) >> 5) * M + ((tid +   0) & 31) * 4]);
        pf1 = *reinterpret_cast<const float4*>(&S[base + (long)((tid + 256) >> 5) * M + ((tid + 256) & 31) * 4]);
        pf2 = *reinterpret_cast<const float4*>(&S[base + (long)((tid + 512) >> 5) * M + ((tid + 512) & 31) * 4]);
        pf3 = *reinterpret_cast<const float4*>(&S[base + (long)((tid + 768) >> 5) * M + ((tid + 768) & 31) * 4]);
    };
    auto stS = [&](int buf) {
        float* b = &Ss[buf * 4096];
        *reinterpret_cast<float4*>(&b[((tid +   0) >> 5) * 128 + ((tid +   0) & 31) * 4]) = pf0;
        *reinterpret_cast<float4*>(&b[((tid + 256) >> 5) * 128 + ((tid + 256) & 31) * 4]) = pf1;
        *reinterpret_cast<float4*>(&b[((tid + 512) >> 5) * 128 + ((tid + 512) & 31) * 4]) = pf2;
        *reinterpret_cast<float4*>(&b[((tid + 768) >> 5) * 128 + ((tid + 768) & 31) * 4]) = pf3;
    };

    ldS(0);
    stS(0);
    __syncthreads();

    const int i0 = (tid >> 4) * 8;
    const int c0 = (tid & 15) * 8;

    u64 acc[8][4];
#pragma unroll
    for (int i = 0; i < 8; i++)
#pragma unroll
        for (int c = 0; c < 4; c++) acc[i][c] = 0ull;

    for (int kb = 0; kb < KB_STEPS; kb++) {
        if (kb + 1 < KB_STEPS) ldS(kb + 1);
        const float* wbase = &Wt[(kb * 32) * WPAD + i0];
        const float* sbase = &Ss[(kb & 1) * 4096 + c0];
#pragma unroll 8
        for (int kk = 0; kk < 32; kk++) {
            const float4 wa = *reinterpret_cast<const float4*>(wbase + kk * WPAD);
            const float4 wb = *reinterpret_cast<const float4*>(wbase + kk * WPAD + 4);
            const u64* sp = reinterpret_cast<const u64*>(sbase + kk * 128);
            const u64 sv0 = sp[0], sv1 = sp[1], sv2 = sp[2], sv3 = sp[3];
            u64 w;
            w = dup2(wa.x); ffma2(acc[0][0], sv0, w); ffma2(acc[0][1], sv1, w); ffma2(acc[0][2], sv2, w); ffma2(acc[0][3], sv3, w);
            w = dup2(wa.y); ffma2(acc[1][0], sv0, w); ffma2(acc[1][1], sv1, w); ffma2(acc[1][2], sv2, w); ffma2(acc[1][3], sv3, w);
            w = dup2(wa.z); ffma2(acc[2][0], sv0, w); ffma2(acc[2][1], sv1, w); ffma2(acc[2][2], sv2, w); ffma2(acc[2][3], sv3, w);
            w = dup2(wa.w); ffma2(acc[3][0], sv0, w); ffma2(acc[3][1], sv1, w); ffma2(acc[3][2], sv2, w); ffma2(acc[3][3], sv3, w);
            w = dup2(wb.x); ffma2(acc[4][0], sv0, w); ffma2(acc[4][1], sv1, w); ffma2(acc[4][2], sv2, w); ffma2(acc[4][3], sv3, w);
            w = dup2(wb.y); ffma2(acc[5][0], sv0, w); ffma2(acc[5][1], sv1, w); ffma2(acc[5][2], sv2, w); ffma2(acc[5][3], sv3, w);
            w = dup2(wb.z); ffma2(acc[6][0], sv0, w); ffma2(acc[6][1], sv1, w); ffma2(acc[6][2], sv2, w); ffma2(acc[6][3], sv3, w);
            w = dup2(wb.w); ffma2(acc[7][0], sv0, w); ffma2(acc[7][1], sv1, w); ffma2(acc[7][2], sv2, w); ffma2(acc[7][3], sv3, w);
        }
        if (kb + 1 < KB_STEPS) {
            __syncthreads();
            stS((kb + 1) & 1);
            __syncthreads();
        }
    }

#pragma unroll
    for (int i = 0; i < 8; i++) {
        u64* op = reinterpret_cast<u64*>(&oc[(long)(i0 + i) * M + ct + c0]);
        op[0] = acc[i][0]; op[1] = acc[i][1]; op[2] = acc[i][2]; op[3] = acc[i][3];
    }
}

// ---------------------------------------------------------------------------
// Inputs (metadata order): g0,g1,g2 (128x128), v0,v1,v2 (128x512),
// s0,s1,s2 (128x512x512). Output: [v0', s0', v1', s1', v2', s2'] flattened.
// ---------------------------------------------------------------------------
extern "C" void kernel_launch(void* const* d_in, const int* in_sizes, int n_in,
                              void* d_out, int out_size)
{
    const float* g0 = (const float*)d_in[0];
    const float* g1 = (const float*)d_in[1];
    const float* g2 = (const float*)d_in[2];
    const float* v0 = (const float*)d_in[3];
    const float* v1 = (const float*)d_in[4];
    const float* v2 = (const float*)d_in[5];
    const float* s0 = (const float*)d_in[6];
    const float* s1 = (const float*)d_in[7];
    const float* s2 = (const float*)d_in[8];
    float* out = (float*)d_out;

    const size_t SMEM = (size_t)(128 * WPAD + 2 * 32 * 128) * sizeof(float); // 100352 B
    cudaFuncSetAttribute(gemm128, cudaFuncAttributeMaxDynamicSharedMemorySize, (int)SMEM);

    void* invp = nullptr;
    cudaGetSymbolAddress(&invp, g_invgT);
    const float* ig = (const float*)invp;

    const long comp_stride = 65536L + 33554432L;   // one (v', s') section per component

    // vn = g^T v : Wt source is g itself (g[k*128+i] == g^T[i][k]); M = 512
    gemm128<<<dim3(4, 3), 256, SMEM>>>(g0, g1, g2, v0, v1, v2, out, comp_stride, 512);

    // invert the three g's (transposed result into g_invgT)
    invert_kernel<<<3, 256>>>(g0, g1, g2);

    // sn = inv(g) s : Wt source = invgT per component; M = 512*512
    gemm128<<<dim3(2048, 3), 256, SMEM>>>(ig, ig + 16384, ig + 32768,
                                          s0, s1, s2, out + 65536, comp_stride, 262144);
}

// round 4
// speedup vs baseline: 1.4669x; 1.4625x over previous
#include <cuda_runtime.h>
#include <cuda_bf16.h>
#include <cstdint>

typedef unsigned int u32;
typedef unsigned long long u64;

#define CS (65536L + 33554432L)   // per-component output stride (vn + sn)

// ---------------- device scratch (no cudaMalloc allowed) -------------------
__device__ float g_invT[3 * 128 * 128];          // inv(g) stored [k][m]
__device__ unsigned short g_Ahi[6 * 16384];      // swizzled bf16 A images (hi)
__device__ unsigned short g_Alo[6 * 16384];      // swizzled bf16 A images (lo)

// ---------------- helpers ----------------------------------------------
__device__ __forceinline__ u32 smem_u32(const void* p) {
    u32 a;
    asm("{ .reg .u64 t; cvta.to.shared.u64 t, %1; cvt.u32.u64 %0, t; }" : "=r"(a) : "l"(p));
    return a;
}
// pack(a,b): b -> high half, a -> low half
__device__ __forceinline__ u32 cvt2(float a, float b) {
    u32 r;
    asm("cvt.rn.bf16x2.f32 %0, %1, %2;" : "=r"(r) : "f"(b), "f"(a));
    return r;
}
__device__ __forceinline__ void ldsm_x4(u32& r0, u32& r1, u32& r2, u32& r3, u32 addr) {
    asm volatile("ldmatrix.sync.aligned.m8n8.x4.shared.b16 {%0,%1,%2,%3}, [%4];"
                 : "=r"(r0), "=r"(r1), "=r"(r2), "=r"(r3) : "r"(addr));
}
__device__ __forceinline__ void ldsm_x4_t(u32& r0, u32& r1, u32& r2, u32& r3, u32 addr) {
    asm volatile("ldmatrix.sync.aligned.m8n8.x4.trans.shared.b16 {%0,%1,%2,%3}, [%4];"
                 : "=r"(r0), "=r"(r1), "=r"(r2), "=r"(r3) : "r"(addr));
}
__device__ __forceinline__ void mma16816(float* c, const u32* a, const u32* b) {
    asm volatile("mma.sync.aligned.m16n8k16.row.col.f32.bf16.bf16.f32 "
                 "{%0,%1,%2,%3}, {%4,%5,%6,%7}, {%8,%9}, {%0,%1,%2,%3};"
                 : "+f"(c[0]), "+f"(c[1]), "+f"(c[2]), "+f"(c[3])
                 : "r"(a[0]), "r"(a[1]), "r"(a[2]), "r"(a[3]), "r"(b[0]), "r"(b[1]));
}

// ---------------------------------------------------------------------------
// Gauss-Jordan inversion, one 128x128 per block. Writes inv(g) as [k][m].
// ---------------------------------------------------------------------------
__global__ void __launch_bounds__(256) invert_kernel(const float* __restrict__ G0,
                                                     const float* __restrict__ G1,
                                                     const float* __restrict__ G2)
{
    __shared__ float rowk[256];
    __shared__ float colk[128];
    const float* G = blockIdx.x == 0 ? G0 : (blockIdx.x == 1 ? G1 : G2);
    const int tid = threadIdx.x;
    const int cg = tid & 7;
    const int c0 = cg * 32;
    const int rb = tid >> 3;

    float r[4][32];
#pragma unroll
    for (int a = 0; a < 4; a++) {
        const int i = rb + 32 * a;
#pragma unroll
        for (int c = 0; c < 32; c++) {
            const int gc = c0 + c;
            r[a][c] = (gc < 128) ? G[i * 128 + gc] : ((gc - 128 == i) ? 1.0f : 0.0f);
        }
    }
    for (int k = 0; k < 128; k++) {
        if ((k & 31) == rb) {
            const int a = k >> 5;
#pragma unroll
            for (int c = 0; c < 32; c++) rowk[c0 + c] = r[a][c];
        }
        if (cg == (k >> 5)) {
            const int cc = k & 31;
#pragma unroll
            for (int a = 0; a < 4; a++) colk[rb + 32 * a] = r[a][cc];
        }
        __syncthreads();
        const float rinv = 1.0f / rowk[k];
        const bool active = (c0 + 31 >= k) && (c0 <= k + 128);
        if (active) {
            float rk[32];
#pragma unroll
            for (int c = 0; c < 32; c++) rk[c] = rowk[c0 + c];
#pragma unroll
            for (int a = 0; a < 4; a++) {
                const int i = rb + 32 * a;
                if (i == k) {
#pragma unroll
                    for (int c = 0; c < 32; c++) r[a][c] *= rinv;
                } else {
                    const float m = colk[i] * rinv;
#pragma unroll
                    for (int c = 0; c < 32; c++) r[a][c] -= m * rk[c];
                }
            }
        }
        __syncthreads();
    }
    if (c0 >= 128) {
#pragma unroll
        for (int a = 0; a < 4; a++) {
            const int i = rb + 32 * a;
#pragma unroll
            for (int c = 0; c < 32; c++)
                g_invT[blockIdx.x * (128 * 128) + (c0 - 128 + c) * 128 + i] = r[a][c];
        }
    }
}

// ---------------------------------------------------------------------------
// Build swizzled bf16 hi/lo A-operand images for ldmatrix consumption.
// id = comp*2 + kind; kind 0: A = g^T (vn), kind 1: A = inv(g) (sn).
// Both read src[k*128 + m] = A[m][k]. Layout: row-major [m][k], 256B rows,
// 16B chunk index xor-swizzled with (m & 7).
// ---------------------------------------------------------------------------
__global__ void __launch_bounds__(256) prep_kernel(const float* __restrict__ G0,
                                                   const float* __restrict__ G1,
                                                   const float* __restrict__ G2)
{
    const int id = blockIdx.x;
    const int comp = id >> 1, kind = id & 1;
    const float* Gc = comp == 0 ? G0 : (comp == 1 ? G1 : G2);
    const float* src = kind ? (g_invT + comp * 16384) : Gc;

    for (int e = threadIdx.x; e < 16384; e += 256) {
        const int m = e & 127, k = e >> 7;
        const float x = src[k * 128 + m];
        const __nv_bfloat16 h = __float2bfloat16(x);
        const float hf = __bfloat162float(h);
        const __nv_bfloat16 l = __float2bfloat16(x - hf);
        const u32 off = (u32)(m * 256 + (((k >> 3) ^ (m & 7)) << 4) + (k & 7) * 2);
        g_Ahi[id * 16384 + (off >> 1)] = __bfloat16_as_ushort(h);
        g_Alo[id * 16384 + (off >> 1)] = __bfloat16_as_ushort(l);
    }
}

// ---------------------------------------------------------------------------
// Main kernel: 148 persistent CTAs x 256 threads. Per tile (128 rows x 128
// cols of output): LDG fp32 S-tile -> bf16 hi/lo split -> swizzled STS
// (double buffered) -> mma.sync 3-pass (Ahi*Bhi + Ahi*Blo + Alo*Bhi) ->
// STG fp32. A images live in smem for the whole CTA lifetime.
// ---------------------------------------------------------------------------
#define SM_A_HI 0
#define SM_A_LO 32768
#define SM_B    65536                 // 2 stages x (32KB hi + 32KB lo)
#define SMEM_TOTAL (65536 + 2 * 65536)   // 196608 B

__global__ void __launch_bounds__(256, 1) main_kernel(
    const float* __restrict__ v0, const float* __restrict__ v1, const float* __restrict__ v2,
    const float* __restrict__ s0, const float* __restrict__ s1, const float* __restrict__ s2,
    float* __restrict__ out)
{
    extern __shared__ char smem[];
    const u32 sb = smem_u32(smem);
    const int tid = threadIdx.x, wid = tid >> 5, lane = tid & 31;
    const int bid = blockIdx.x;

    int comp, t0, t1;
    bool sn;
    if (bid < 145) {
        sn = true;
        comp = bid % 3;
        const int nC = (comp == 0) ? 49 : 48;
        const int ci = bid / 3;
        t0 = (ci * 2048) / nC;
        t1 = ((ci + 1) * 2048) / nC;
    } else {
        sn = false;
        comp = bid - 145;
        t0 = 0;
        t1 = 4;
    }
    const int nt = t1 - t0;
    const long Ms = sn ? 262144L : 512L;
    const float* Bsrc = sn ? (comp == 0 ? s0 : comp == 1 ? s1 : s2)
                           : (comp == 0 ? v0 : comp == 1 ? v1 : v2);
    float* obase = out + (long)comp * CS + (sn ? 65536 : 0);
    const int imgid = comp * 2 + (sn ? 1 : 0);

    // copy pre-swizzled A images (32KB hi + 32KB lo)
    {
        const float4* Ah = (const float4*)(g_Ahi + imgid * 16384);
        const float4* Al = (const float4*)(g_Alo + imgid * 16384);
#pragma unroll
        for (int q = 0; q < 8; q++) {
            ((float4*)(smem + SM_A_HI))[q * 256 + tid] = Ah[q * 256 + tid];
            ((float4*)(smem + SM_A_LO))[q * 256 + tid] = Al[q * 256 + tid];
        }
    }
    __syncthreads();

    const int wm = (wid & 3) * 32;       // warp row offset (m)
    const int wn = (wid >> 2) * 64;      // warp col offset (n)

    float4 st[16];
    auto ldtile = [&](int t) {
        const float* src = Bsrc + (long)t * 128;
#pragma unroll
        for (int qq = 0; qq < 16; qq++) {
            const int f = qq * 256 + tid;
            st[qq] = *(const float4*)(src + (long)(f >> 5) * Ms + (f & 31) * 4);
        }
    };
    ldtile(t0);

    for (int j = 0; j < nt; j++) {
        const int p = j & 1;
        char* bp = smem + SM_B + p * 65536;

        // ---- split to hi/lo bf16 and store swizzled ----
#pragma unroll
        for (int qq = 0; qq < 16; qq++) {
            const int f = qq * 256 + tid;
            const int kk = f >> 5, c = (f & 31) * 4;
            const float4 xv = st[qq];
            const u32 h01 = cvt2(xv.x, xv.y);
            const u32 h23 = cvt2(xv.z, xv.w);
            const float fx = __uint_as_float(h01 << 16);
            const float fy = __uint_as_float(h01 & 0xffff0000u);
            const float fz = __uint_as_float(h23 << 16);
            const float fw = __uint_as_float(h23 & 0xffff0000u);
            const u32 l01 = cvt2(xv.x - fx, xv.y - fy);
            const u32 l23 = cvt2(xv.z - fz, xv.w - fw);
            const u32 off = (u32)(kk * 256 + (((c >> 3) ^ (kk & 7)) << 4) + (c & 7) * 2);
            *(uint2*)(bp + off)         = make_uint2(h01, h23);
            *(uint2*)(bp + 32768 + off) = make_uint2(l01, l23);
        }
        __syncthreads();

        // prefetch next tile while computing this one
        if (j + 1 < nt) ldtile(t0 + j + 1);

        // ---- compute: 3-pass bf16 mma over K=128 ----
        const u32 bB_hi = sb + SM_B + p * 65536;
        const u32 bB_lo = bB_hi + 32768;

        float acc[2][8][4];
#pragma unroll
        for (int mi = 0; mi < 2; mi++)
#pragma unroll
            for (int ni = 0; ni < 8; ni++)
#pragma unroll
                for (int x = 0; x < 4; x++) acc[mi][ni][x] = 0.0f;

#pragma unroll
        for (int ks = 0; ks < 8; ks++) {
            u32 ah[2][4], al[2][4];
#pragma unroll
            for (int mi = 0; mi < 2; mi++) {
                const int m = wm + mi * 16 + (lane & 15);
                const u32 chunk = (u32)((ks * 2 + (lane >> 4)) ^ (m & 7));
                const u32 aoff = (u32)(m * 256) + chunk * 16;
                ldsm_x4(ah[mi][0], ah[mi][1], ah[mi][2], ah[mi][3], sb + SM_A_HI + aoff);
                ldsm_x4(al[mi][0], al[mi][1], al[mi][2], al[mi][3], sb + SM_A_LO + aoff);
            }
            u32 bh[8][2], bl[8][2];
#pragma unroll
            for (int v = 0; v < 4; v++) {
                const int k = ks * 16 + (lane & 15);
                const int nb = wn + v * 16 + (lane >> 4) * 8;
                const u32 boff = (u32)(k * 256 + (((nb >> 3) ^ (k & 7)) << 4));
                ldsm_x4_t(bh[2 * v][0], bh[2 * v][1], bh[2 * v + 1][0], bh[2 * v + 1][1], bB_hi + boff);
                ldsm_x4_t(bl[2 * v][0], bl[2 * v][1], bl[2 * v + 1][0], bl[2 * v + 1][1], bB_lo + boff);
            }
#pragma unroll
            for (int mi = 0; mi < 2; mi++)
#pragma unroll
                for (int ni = 0; ni < 8; ni++) {
                    mma16816(acc[mi][ni], ah[mi], bh[ni]);
                    mma16816(acc[mi][ni], ah[mi], bl[ni]);
                    mma16816(acc[mi][ni], al[mi], bh[ni]);
                }
        }

        // ---- epilogue: direct STG ----
        const long tcol = (long)(t0 + j) * 128;
#pragma unroll
        for (int mi = 0; mi < 2; mi++) {
            const int r = wm + mi * 16 + (lane >> 2);
            float* rp = obase + (long)r * Ms + tcol + wn + (lane & 3) * 2;
#pragma unroll
            for (int ni = 0; ni < 8; ni++) {
                *(float2*)(rp + ni * 8)          = make_float2(acc[mi][ni][0], acc[mi][ni][1]);
                *(float2*)(rp + ni * 8 + 8 * Ms) = make_float2(acc[mi][ni][2], acc[mi][ni][3]);
            }
        }
        // no end-of-iter barrier needed: double buffer + the post-STS barrier
        // of iteration j+1 orders reuse of this buffer.
    }
}

// ---------------------------------------------------------------------------
// Inputs (metadata order): g0,g1,g2 (128x128), v0,v1,v2 (128x512),
// s0,s1,s2 (128x512x512). Output: [v0', s0', v1', s1', v2', s2'] flattened.
// ---------------------------------------------------------------------------
extern "C" void kernel_launch(void* const* d_in, const int* in_sizes, int n_in,
                              void* d_out, int out_size)
{
    const float* g0 = (const float*)d_in[0];
    const float* g1 = (const float*)d_in[1];
    const float* g2 = (const float*)d_in[2];
    const float* v0 = (const float*)d_in[3];
    const float* v1 = (const float*)d_in[4];
    const float* v2 = (const float*)d_in[5];
    const float* s0 = (const float*)d_in[6];
    const float* s1 = (const float*)d_in[7];
    const float* s2 = (const float*)d_in[8];
    float* out = (float*)d_out;

    cudaFuncSetAttribute(main_kernel, cudaFuncAttributeMaxDynamicSharedMemorySize, SMEM_TOTAL);

    invert_kernel<<<3, 256>>>(g0, g1, g2);
    prep_kernel<<<6, 256>>>(g0, g1, g2);
    main_kernel<<<148, 256, SMEM_TOTAL>>>(v0, v1, v2, s0, s1, s2, out);
}

// round 5
// speedup vs baseline: 2.4620x; 1.6784x over previous
#include <cuda_runtime.h>
#include <cstdint>

typedef unsigned int u32;
typedef unsigned long long u64;

#define CS (65536L + 33554432L)   // per-component output stride (vn + sn)

// Swizzled tf32 A-operand images: id = comp*2 + kind (0: g^T for vn, 1: inv(g) for sn)
__device__ float g_Atf[6 * 16384];

// ---------------- helpers ---------------------------------------------------
__device__ __forceinline__ u32 smem_u32(const void* p) {
    u32 a;
    asm("{ .reg .u64 t; cvta.to.shared.u64 t, %1; cvt.u32.u64 %0, t; }" : "=r"(a) : "l"(p));
    return a;
}
__device__ __forceinline__ float to_tf32(float x) {
    float r;
    asm("cvt.rna.tf32.f32 %0, %1;" : "=f"(r) : "f"(x));
    return r;
}
__device__ __forceinline__ u32 lds32(u32 a) {
    u32 v;
    asm volatile("ld.shared.b32 %0, [%1];" : "=r"(v) : "r"(a));
    return v;
}
__device__ __forceinline__ void mma16808(float* c, const u32* a, const u32* b) {
    asm volatile("mma.sync.aligned.m16n8k8.row.col.f32.tf32.tf32.f32 "
                 "{%0,%1,%2,%3}, {%4,%5,%6,%7}, {%8,%9}, {%0,%1,%2,%3};"
                 : "+f"(c[0]), "+f"(c[1]), "+f"(c[2]), "+f"(c[3])
                 : "r"(a[0]), "r"(a[1]), "r"(a[2]), "r"(a[3]), "r"(b[0]), "r"(b[1]));
}
// swizzled [row][k] image offset: 512 B rows, 16 B chunks XOR (row & 7)
__device__ __forceinline__ u32 img_off(int m, int k) {
    return (u32)(m * 512 + (((k >> 2) ^ (m & 7)) << 4) + (k & 3) * 4);
}

// ---------------------------------------------------------------------------
// Blocks 0-2: Gauss-Jordan inversion of one 128x128 per block (registers,
// ALL indices static -> no local-memory demotion). Warp = column chunk so
// pivot-column publish and active-window gate are warp-uniform.
// Writes the swizzled tf32 image of inv(g) directly (kind 1).
// Blocks 3-5: build the g^T image (kind 0).
// ---------------------------------------------------------------------------
__global__ void __launch_bounds__(256) invert_kernel(const float* __restrict__ G0,
                                                     const float* __restrict__ G1,
                                                     const float* __restrict__ G2)
{
    __shared__ float rowk[256];
    __shared__ float colk[128];
    const int b = blockIdx.x;
    const int tid = threadIdx.x;

    if (b >= 3) {   // prep: A = g^T, image id = comp*2
        const float* src = (b == 3) ? G0 : (b == 4 ? G1 : G2);
        const int id = (b - 3) * 2;
        for (int e = tid; e < 16384; e += 256) {
            const int m = e & 127, k = e >> 7;
            g_Atf[id * 16384 + (img_off(m, k) >> 2)] = to_tf32(src[k * 128 + m]);
        }
        return;
    }

    const float* G = b == 0 ? G0 : (b == 1 ? G1 : G2);
    const int cg = tid >> 5;        // warp id = column chunk
    const int c0 = cg * 32;
    const int rb = tid & 31;        // row within 32-row band

    float r[4][32];
#pragma unroll
    for (int a = 0; a < 4; a++) {
        const int i = rb + 32 * a;
#pragma unroll
        for (int c = 0; c < 32; c++) {
            const int gc = c0 + c;
            r[a][c] = (gc < 128) ? G[i * 128 + gc] : ((gc - 128 == i) ? 1.0f : 0.0f);
        }
    }

    for (int k = 0; k < 128; k++) {
        const int kl = k & 31, kh = k >> 5;
        // publish pivot row (uniform arm select -> static reg indices)
        if (rb == kl) {
#pragma unroll
            for (int a = 0; a < 4; a++) if (a == kh) {
#pragma unroll
                for (int c = 0; c < 32; c++) rowk[c0 + c] = r[a][c];
            }
        }
        // publish pivot column (one warp; uniform arm select)
        if (cg == kh) {
#pragma unroll
            for (int t = 0; t < 32; t++) if (t == kl) {
#pragma unroll
                for (int a = 0; a < 4; a++) colk[rb + 32 * a] = r[a][t];
            }
        }
        __syncthreads();
        const float rinv = 1.0f / rowk[k];
        // active column window [k, k+128]; warp-uniform -> real branch
        if (c0 + 31 >= k && c0 <= k + 128) {
            float rk[32];
#pragma unroll
            for (int c = 0; c < 32; c++) rk[c] = rowk[c0 + c];
#pragma unroll
            for (int a = 0; a < 4; a++) {
                const int i = rb + 32 * a;
                if (i == k) {
#pragma unroll
                    for (int c = 0; c < 32; c++) r[a][c] *= rinv;
                } else {
                    const float m = colk[i] * rinv;
#pragma unroll
                    for (int c = 0; c < 32; c++) r[a][c] -= m * rk[c];
                }
            }
        }
        __syncthreads();
    }

    // right half = inverse; write swizzled tf32 image (kind 1)
    if (cg >= 4) {
        const int id = b * 2 + 1;
#pragma unroll
        for (int a = 0; a < 4; a++) {
            const int i = rb + 32 * a;
#pragma unroll
            for (int c = 0; c < 32; c++)
                g_Atf[id * 16384 + (img_off(i, c0 - 128 + c) >> 2)] = to_tf32(r[a][c]);
        }
    }
}

// ---------------------------------------------------------------------------
// Main kernel: 148 persistent CTAs x 256 threads. Tile = 128 rows x 128 cols.
// Single-pass tf32 mma.m16n8k8. A image resident in smem; B tile:
// LDG fp32 (k-strided quads) -> cvt.rna.tf32 -> swizzled STS [n][k]
// (double-buffered). Warp tile 32m x 64n, direct fp32 STG epilogue.
// ---------------------------------------------------------------------------
#define SM_A 0
#define SM_B 65536                       // 2 stages x 64 KB
#define SMEM_TOTAL (65536 * 3)           // 192 KB

__global__ void __launch_bounds__(256, 1) main_kernel(
    const float* __restrict__ v0, const float* __restrict__ v1, const float* __restrict__ v2,
    const float* __restrict__ s0, const float* __restrict__ s1, const float* __restrict__ s2,
    float* __restrict__ out)
{
    extern __shared__ char smem[];
    const u32 sb = smem_u32(smem);
    const int tid = threadIdx.x, wid = tid >> 5, lane = tid & 31;
    const int bid = blockIdx.x;

    int comp, t0, t1;
    bool sn;
    if (bid < 145) {
        sn = true;
        comp = bid % 3;
        const int nC = (comp == 0) ? 49 : 48;
        const int ci = bid / 3;
        t0 = (ci * 2048) / nC;
        t1 = ((ci + 1) * 2048) / nC;
    } else {
        sn = false;
        comp = bid - 145;
        t0 = 0;
        t1 = 4;
    }
    const int nt = t1 - t0;
    const long Ms = sn ? 262144L : 512L;
    const float* Bsrc = sn ? (comp == 0 ? s0 : comp == 1 ? s1 : s2)
                           : (comp == 0 ? v0 : comp == 1 ? v1 : v2);
    float* obase = out + (long)comp * CS + (sn ? 65536 : 0);
    const int imgid = comp * 2 + (sn ? 1 : 0);

    // copy pre-swizzled tf32 A image (64 KB)
    {
        const float4* Ai = (const float4*)(g_Atf + imgid * 16384);
#pragma unroll
        for (int q = 0; q < 16; q++)
            ((float4*)(smem + SM_A))[q * 256 + tid] = Ai[q * 256 + tid];
    }
    __syncthreads();

    const int wm = (wid & 3) * 32;       // warp row offset (m)
    const int wn = (wid >> 2) * 64;      // warp col offset (n)
    const int gidr = lane >> 2;          // groupID (0..7)
    const int gidc = lane & 3;           // threadID-in-group (0..3)

    float st[64];
    auto ldtile = [&](int t) {
        const float* src = Bsrc + (long)t * 128;
#pragma unroll
        for (int q = 0; q < 16; q++) {
            const int e = q * 256 + tid;          // chunk id: n = e&127, kc = e>>7
            const int n = e & 127;
            const float* pp = src + (long)((e >> 7) * 4) * Ms + n;
            st[q * 4 + 0] = pp[0];
            st[q * 4 + 1] = pp[Ms];
            st[q * 4 + 2] = pp[Ms * 2];
            st[q * 4 + 3] = pp[Ms * 3];
        }
    };
    ldtile(t0);

    for (int j = 0; j < nt; j++) {
        const int p = j & 1;

        // ---- convert + swizzled store: B[n][k] tf32 ----
        char* bp = smem + SM_B + p * 65536;
#pragma unroll
        for (int q = 0; q < 16; q++) {
            const int e = q * 256 + tid;
            const int n = e & 127, kc = e >> 7;
            float4 v = make_float4(to_tf32(st[q * 4 + 0]), to_tf32(st[q * 4 + 1]),
                                   to_tf32(st[q * 4 + 2]), to_tf32(st[q * 4 + 3]));
            *(float4*)(bp + n * 512 + ((kc ^ (n & 7)) << 4)) = v;
        }
        __syncthreads();

        // prefetch next tile during compute
        if (j + 1 < nt) ldtile(t0 + j + 1);

        // ---- compute: single-pass tf32 mma over K=128 (16 k-steps) ----
        const u32 bA = sb + SM_A;
        const u32 bB = sb + SM_B + p * 65536;

        float acc[2][8][4];
#pragma unroll
        for (int mi = 0; mi < 2; mi++)
#pragma unroll
            for (int ni = 0; ni < 8; ni++)
#pragma unroll
                for (int x = 0; x < 4; x++) acc[mi][ni][x] = 0.0f;

#pragma unroll
        for (int ks = 0; ks < 16; ks++) {
            u32 av[2][4];
#pragma unroll
            for (int mi = 0; mi < 2; mi++) {
                const int m0 = wm + mi * 16 + gidr;          // m0&7 == gidr
                const u32 r0 = bA + m0 * 512 + gidc * 4;
                const u32 r1 = bA + (m0 + 8) * 512 + gidc * 4;
                av[mi][0] = lds32(r0 + (((2 * ks) ^ gidr) << 4));
                av[mi][1] = lds32(r1 + (((2 * ks) ^ gidr) << 4));
                av[mi][2] = lds32(r0 + (((2 * ks + 1) ^ gidr) << 4));
                av[mi][3] = lds32(r1 + (((2 * ks + 1) ^ gidr) << 4));
            }
            u32 bv[8][2];
#pragma unroll
            for (int ni = 0; ni < 8; ni++) {
                const int n = wn + ni * 8 + gidr;            // n&7 == gidr
                const u32 rr = bB + n * 512 + gidc * 4;
                bv[ni][0] = lds32(rr + (((2 * ks) ^ gidr) << 4));
                bv[ni][1] = lds32(rr + (((2 * ks + 1) ^ gidr) << 4));
            }
#pragma unroll
            for (int mi = 0; mi < 2; mi++)
#pragma unroll
                for (int ni = 0; ni < 8; ni++)
                    mma16808(acc[mi][ni], av[mi], bv[ni]);
        }

        // ---- epilogue: direct fp32 STG ----
        const long tcol = (long)(t0 + j) * 128;
#pragma unroll
        for (int mi = 0; mi < 2; mi++) {
            const int r = wm + mi * 16 + gidr;
            float* rp = obase + (long)r * Ms + tcol + wn + gidc * 2;
#pragma unroll
            for (int ni = 0; ni < 8; ni++) {
                *(float2*)(rp + ni * 8)          = make_float2(acc[mi][ni][0], acc[mi][ni][1]);
                *(float2*)(rp + ni * 8 + 8 * Ms) = make_float2(acc[mi][ni][2], acc[mi][ni][3]);
            }
        }
        // double buffer + next iteration's post-STS barrier orders buffer reuse
    }
}

// ---------------------------------------------------------------------------
// Inputs (metadata order): g0,g1,g2 (128x128), v0,v1,v2 (128x512),
// s0,s1,s2 (128x512x512). Output: [v0', s0', v1', s1', v2', s2'] flattened.
// ---------------------------------------------------------------------------
extern "C" void kernel_launch(void* const* d_in, const int* in_sizes, int n_in,
                              void* d_out, int out_size)
{
    const float* g0 = (const float*)d_in[0];
    const float* g1 = (const float*)d_in[1];
    const float* g2 = (const float*)d_in[2];
    const float* v0 = (const float*)d_in[3];
    const float* v1 = (const float*)d_in[4];
    const float* v2 = (const float*)d_in[5];
    const float* s0 = (const float*)d_in[6];
    const float* s1 = (const float*)d_in[7];
    const float* s2 = (const float*)d_in[8];
    float* out = (float*)d_out;

    cudaFuncSetAttribute(main_kernel, cudaFuncAttributeMaxDynamicSharedMemorySize, SMEM_TOTAL);

    invert_kernel<<<6, 256>>>(g0, g1, g2);   // blocks 0-2 invert, 3-5 prep g^T
    main_kernel<<<148, 256, SMEM_TOTAL>>>(v0, v1, v2, s0, s1, s2, out);
}